// round 1
// baseline (speedup 1.0000x reference)
#include <cuda_runtime.h>
#include <cuda_bf16.h>
#include <math.h>

// Problem constants
#define D       256
#define MAXROWS 8192
#define LOG_NORM 2.0767937f          // -0.5*ln(2*pi) - ln(0.05)
#define HALF_INV_SIG2 200.0f         // 0.5 / sigma^2, sigma = 0.05
#define COS_THRESH 0.25f             // below this, exp underflows to ~0 in fp32

// Normalized copies of Ex / Ey (scratch; device globals per harness rules)
__device__ float g_xn[MAXROWS * D];
__device__ float g_yn[MAXROWS * D];

// ---------------------------------------------------------------------------
// Row normalization: one warp per row. D=256 floats = 64 float4 per row.
// ---------------------------------------------------------------------------
__global__ void __launch_bounds__(256) normalize_kernel(
    const float* __restrict__ Ex, const float* __restrict__ Ey, int N, int M)
{
    int warp = threadIdx.x >> 5;
    int lane = threadIdx.x & 31;
    int row  = blockIdx.x * 8 + warp;
    if (row >= N + M) return;

    const float* src;
    float* dst;
    int r;
    if (row < N) { src = Ex; dst = g_xn; r = row; }
    else         { src = Ey; dst = g_yn; r = row - N; }

    const float4* s4 = reinterpret_cast<const float4*>(src + (size_t)r * D);
    float4 v0 = s4[lane];
    float4 v1 = s4[lane + 32];

    float ss = v0.x*v0.x + v0.y*v0.y + v0.z*v0.z + v0.w*v0.w
             + v1.x*v1.x + v1.y*v1.y + v1.z*v1.z + v1.w*v1.w;
    #pragma unroll
    for (int off = 16; off > 0; off >>= 1)
        ss += __shfl_xor_sync(0xFFFFFFFFu, ss, off);

    float inv = 1.0f / fmaxf(sqrtf(ss), 1e-8f);

    v0.x *= inv; v0.y *= inv; v0.z *= inv; v0.w *= inv;
    v1.x *= inv; v1.y *= inv; v1.z *= inv; v1.w *= inv;

    float4* d4 = reinterpret_cast<float4*>(dst + (size_t)r * D);
    d4[lane]      = v0;
    d4[lane + 32] = v1;
}

// ---------------------------------------------------------------------------
// Fused GEMM + gaussian-of-cosine epilogue + column reduction.
// Block tile: 128 (n) x 128 (m), BK=16. 256 threads, 8x8 micro-tile each.
// cos[n,m] = xn[n,:] . yn[m,:]   (both K-contiguous row-major)
// out[m] += sum_n exp(LOG_NORM - 200*(cos-1)^2), thresholded.
// ---------------------------------------------------------------------------
__global__ void __launch_bounds__(256, 2) cosexp_gemm(
    int N, int M, float* __restrict__ out)
{
    __shared__ __align__(16) float As[16][132];   // [k][n-in-tile], +4 pad
    __shared__ __align__(16) float Bs[16][132];   // [k][m-in-tile]
    __shared__ float colAcc[128];

    const int t  = threadIdx.x;
    const int tx = t & 15;        // m sub-tile
    const int ty = t >> 4;        // n sub-tile
    const int mBase = blockIdx.x * 128;
    const int nBase = blockIdx.y * 128;

    if (t < 128) colAcc[t] = 0.0f;

    const float* Aptr = g_xn + (size_t)nBase * D;
    const float* Bptr = g_yn + (size_t)mBase * D;

    float acc[8][8];
    #pragma unroll
    for (int i = 0; i < 8; i++)
        #pragma unroll
        for (int j = 0; j < 8; j++) acc[i][j] = 0.0f;

    // Each thread loads 2 float4 from A and 2 from B per k-tile.
    // f in [0,512): row = f>>2, kq = f&3 (4 float4 per 16-wide k slice).
    float4 aReg[2], bReg[2];

    #pragma unroll
    for (int q = 0; q < 2; q++) {
        int f   = t + q * 256;
        int row = f >> 2;
        int kq  = f & 3;
        aReg[q] = *reinterpret_cast<const float4*>(Aptr + row * D + kq * 4);
        bReg[q] = *reinterpret_cast<const float4*>(Bptr + row * D + kq * 4);
    }
    #pragma unroll
    for (int q = 0; q < 2; q++) {
        int f   = t + q * 256;
        int row = f >> 2;
        int kq  = f & 3;
        As[kq*4+0][row] = aReg[q].x; As[kq*4+1][row] = aReg[q].y;
        As[kq*4+2][row] = aReg[q].z; As[kq*4+3][row] = aReg[q].w;
        Bs[kq*4+0][row] = bReg[q].x; Bs[kq*4+1][row] = bReg[q].y;
        Bs[kq*4+2][row] = bReg[q].z; Bs[kq*4+3][row] = bReg[q].w;
    }
    __syncthreads();

    const int NKT = D / 16;  // 16 k-tiles
    for (int kt = 0; kt < NKT; kt++) {
        // Prefetch next tile into registers (hides LDG under compute)
        if (kt < NKT - 1) {
            int kOff = (kt + 1) * 16;
            #pragma unroll
            for (int q = 0; q < 2; q++) {
                int f   = t + q * 256;
                int row = f >> 2;
                int kq  = f & 3;
                aReg[q] = *reinterpret_cast<const float4*>(Aptr + row * D + kOff + kq * 4);
                bReg[q] = *reinterpret_cast<const float4*>(Bptr + row * D + kOff + kq * 4);
            }
        }

        // Compute on current smem tile
        #pragma unroll
        for (int kk = 0; kk < 16; kk++) {
            float4 a0 = *reinterpret_cast<const float4*>(&As[kk][ty * 8]);
            float4 a1 = *reinterpret_cast<const float4*>(&As[kk][ty * 8 + 4]);
            float4 b0 = *reinterpret_cast<const float4*>(&Bs[kk][tx * 8]);
            float4 b1 = *reinterpret_cast<const float4*>(&Bs[kk][tx * 8 + 4]);
            float a[8] = {a0.x, a0.y, a0.z, a0.w, a1.x, a1.y, a1.z, a1.w};
            float b[8] = {b0.x, b0.y, b0.z, b0.w, b1.x, b1.y, b1.z, b1.w};
            #pragma unroll
            for (int i = 0; i < 8; i++)
                #pragma unroll
                for (int j = 0; j < 8; j++)
                    acc[i][j] = fmaf(a[i], b[j], acc[i][j]);
        }
        __syncthreads();

        if (kt < NKT - 1) {
            #pragma unroll
            for (int q = 0; q < 2; q++) {
                int f   = t + q * 256;
                int row = f >> 2;
                int kq  = f & 3;
                As[kq*4+0][row] = aReg[q].x; As[kq*4+1][row] = aReg[q].y;
                As[kq*4+2][row] = aReg[q].z; As[kq*4+3][row] = aReg[q].w;
                Bs[kq*4+0][row] = bReg[q].x; Bs[kq*4+1][row] = bReg[q].y;
                Bs[kq*4+2][row] = bReg[q].z; Bs[kq*4+3][row] = bReg[q].w;
            }
            __syncthreads();
        }
    }

    // Epilogue: thresholded gaussian + column sums.
    // cos <= COS_THRESH -> exp underflows to 0 in fp32 (matches reference).
    #pragma unroll
    for (int j = 0; j < 8; j++) {
        float cs = 0.0f;
        #pragma unroll
        for (int i = 0; i < 8; i++) {
            float c = acc[i][j];
            if (c > COS_THRESH) {
                float d = c - 1.0f;
                cs += expf(LOG_NORM - HALF_INV_SIG2 * d * d);
            }
        }
        if (cs != 0.0f) atomicAdd(&colAcc[tx * 8 + j], cs);
    }
    __syncthreads();

    if (t < 128) {
        float v = colAcc[t];
        if (v != 0.0f) atomicAdd(&out[mBase + t], v);
    }
}

// ---------------------------------------------------------------------------
extern "C" void kernel_launch(void* const* d_in, const int* in_sizes, int n_in,
                              void* d_out, int out_size)
{
    const float* Ex = (const float*)d_in[0];
    const float* Ey = (const float*)d_in[1];
    float* out = (float*)d_out;

    int N = in_sizes[0] / D;   // 8192
    int M = in_sizes[1] / D;   // 8192

    cudaMemsetAsync(out, 0, (size_t)out_size * sizeof(float));

    int normBlocks = (N + M + 7) / 8;
    normalize_kernel<<<normBlocks, 256>>>(Ex, Ey, N, M);

    dim3 grid(M / 128, N / 128);
    cosexp_gemm<<<grid, 256>>>(N, M, out);
}

// round 2
// speedup vs baseline: 1.0422x; 1.0422x over previous
#include <cuda_runtime.h>
#include <cuda_bf16.h>
#include <math.h>

// Problem constants
#define D       256
#define MAXROWS 8192
#define LOG_NORM 2.0767937f          // -0.5*ln(2*pi) - ln(0.05)
#define HALF_INV_SIG2 200.0f         // 0.5 / sigma^2, sigma = 0.05
#define COS_THRESH 0.25f             // below this, exp underflows to ~0 in fp32

// Normalized copies of Ex / Ey (scratch; device globals per harness rules)
__device__ float g_xn[MAXROWS * D];
__device__ float g_yn[MAXROWS * D];

// ---------------------------------------------------------------------------
// Row normalization: one warp per row. D=256 floats = 64 float4 per row.
// ---------------------------------------------------------------------------
__global__ void __launch_bounds__(256) normalize_kernel(
    const float* __restrict__ Ex, const float* __restrict__ Ey, int N, int M)
{
    int warp = threadIdx.x >> 5;
    int lane = threadIdx.x & 31;
    int row  = blockIdx.x * 8 + warp;
    if (row >= N + M) return;

    const float* src;
    float* dst;
    int r;
    if (row < N) { src = Ex; dst = g_xn; r = row; }
    else         { src = Ey; dst = g_yn; r = row - N; }

    const float4* s4 = reinterpret_cast<const float4*>(src + (size_t)r * D);
    float4 v0 = s4[lane];
    float4 v1 = s4[lane + 32];

    float ss = v0.x*v0.x + v0.y*v0.y + v0.z*v0.z + v0.w*v0.w
             + v1.x*v1.x + v1.y*v1.y + v1.z*v1.z + v1.w*v1.w;
    #pragma unroll
    for (int off = 16; off > 0; off >>= 1)
        ss += __shfl_xor_sync(0xFFFFFFFFu, ss, off);

    float inv = 1.0f / fmaxf(sqrtf(ss), 1e-8f);

    v0.x *= inv; v0.y *= inv; v0.z *= inv; v0.w *= inv;
    v1.x *= inv; v1.y *= inv; v1.z *= inv; v1.w *= inv;

    float4* d4 = reinterpret_cast<float4*>(dst + (size_t)r * D);
    d4[lane]      = v0;
    d4[lane + 32] = v1;
}

// ---------------------------------------------------------------------------
// Fused GEMM + gaussian-of-cosine epilogue + column reduction.
// Block tile: 128 (n) x 128 (m), BK=16, double-buffered smem (1 sync/tile).
// 256 threads, 8x8 micro-tile per thread, computed with packed fma.rn.f32x2
// (FFMA2): acc pair (j, j+1) updated per instruction.
// ---------------------------------------------------------------------------
__global__ void __launch_bounds__(256, 2) cosexp_gemm(
    int N, int M, float* __restrict__ out)
{
    __shared__ __align__(16) float As[2][16][132];   // [stage][k][n-in-tile]
    __shared__ __align__(16) float Bs[2][16][132];   // [stage][k][m-in-tile]
    __shared__ float colAcc[128];

    const int t  = threadIdx.x;
    const int tx = t & 15;        // m sub-tile
    const int ty = t >> 4;        // n sub-tile
    const int mBase = blockIdx.x * 128;
    const int nBase = blockIdx.y * 128;

    if (t < 128) colAcc[t] = 0.0f;

    const float* Aptr = g_xn + (size_t)nBase * D;
    const float* Bptr = g_yn + (size_t)mBase * D;

    // Packed accumulators: acc2[i][jp] holds (acc[i][2jp], acc[i][2jp+1])
    unsigned long long acc2[8][4];
    #pragma unroll
    for (int i = 0; i < 8; i++)
        #pragma unroll
        for (int jp = 0; jp < 4; jp++) acc2[i][jp] = 0ULL;

    // Loader mapping: f in [0,512): row = f>>2, kq = f&3
    const int row0 = t >> 2,          kq0 = t & 3;
    const int row1 = (t + 256) >> 2,  kq1 = (t + 256) & 3;

    float4 aReg[2], bReg[2];

    // Preload tile 0 into stage 0
    aReg[0] = *reinterpret_cast<const float4*>(Aptr + row0 * D + kq0 * 4);
    bReg[0] = *reinterpret_cast<const float4*>(Bptr + row0 * D + kq0 * 4);
    aReg[1] = *reinterpret_cast<const float4*>(Aptr + row1 * D + kq1 * 4);
    bReg[1] = *reinterpret_cast<const float4*>(Bptr + row1 * D + kq1 * 4);

    As[0][kq0*4+0][row0] = aReg[0].x; As[0][kq0*4+1][row0] = aReg[0].y;
    As[0][kq0*4+2][row0] = aReg[0].z; As[0][kq0*4+3][row0] = aReg[0].w;
    Bs[0][kq0*4+0][row0] = bReg[0].x; Bs[0][kq0*4+1][row0] = bReg[0].y;
    Bs[0][kq0*4+2][row0] = bReg[0].z; Bs[0][kq0*4+3][row0] = bReg[0].w;
    As[0][kq1*4+0][row1] = aReg[1].x; As[0][kq1*4+1][row1] = aReg[1].y;
    As[0][kq1*4+2][row1] = aReg[1].z; As[0][kq1*4+3][row1] = aReg[1].w;
    Bs[0][kq1*4+0][row1] = bReg[1].x; Bs[0][kq1*4+1][row1] = bReg[1].y;
    Bs[0][kq1*4+2][row1] = bReg[1].z; Bs[0][kq1*4+3][row1] = bReg[1].w;
    __syncthreads();

    const int NKT = D / 16;  // 16 k-tiles
    int s = 0;
    for (int kt = 0; kt < NKT; kt++) {
        // Prefetch next tile into registers (hides LDG under compute)
        if (kt < NKT - 1) {
            int kOff = (kt + 1) * 16;
            aReg[0] = *reinterpret_cast<const float4*>(Aptr + row0 * D + kOff + kq0 * 4);
            bReg[0] = *reinterpret_cast<const float4*>(Bptr + row0 * D + kOff + kq0 * 4);
            aReg[1] = *reinterpret_cast<const float4*>(Aptr + row1 * D + kOff + kq1 * 4);
            bReg[1] = *reinterpret_cast<const float4*>(Bptr + row1 * D + kOff + kq1 * 4);
        }

        // Compute on current smem stage
        #pragma unroll
        for (int kk = 0; kk < 16; kk++) {
            float4 a0 = *reinterpret_cast<const float4*>(&As[s][kk][ty * 8]);
            float4 a1 = *reinterpret_cast<const float4*>(&As[s][kk][ty * 8 + 4]);
            ulonglong2 bq0 = *reinterpret_cast<const ulonglong2*>(&Bs[s][kk][tx * 8]);
            ulonglong2 bq1 = *reinterpret_cast<const ulonglong2*>(&Bs[s][kk][tx * 8 + 4]);

            unsigned long long bp[4] = {bq0.x, bq0.y, bq1.x, bq1.y};
            float av[8] = {a0.x, a0.y, a0.z, a0.w, a1.x, a1.y, a1.z, a1.w};

            unsigned long long ap[8];
            #pragma unroll
            for (int i = 0; i < 8; i++)
                asm("mov.b64 %0, {%1, %1};" : "=l"(ap[i]) : "f"(av[i]));

            #pragma unroll
            for (int i = 0; i < 8; i++)
                #pragma unroll
                for (int jp = 0; jp < 4; jp++)
                    asm("fma.rn.f32x2 %0, %1, %2, %0;"
                        : "+l"(acc2[i][jp]) : "l"(ap[i]), "l"(bp[jp]));
        }

        // Stage next tile, single barrier per iteration (double buffering)
        if (kt < NKT - 1) {
            int ns = s ^ 1;
            As[ns][kq0*4+0][row0] = aReg[0].x; As[ns][kq0*4+1][row0] = aReg[0].y;
            As[ns][kq0*4+2][row0] = aReg[0].z; As[ns][kq0*4+3][row0] = aReg[0].w;
            Bs[ns][kq0*4+0][row0] = bReg[0].x; Bs[ns][kq0*4+1][row0] = bReg[0].y;
            Bs[ns][kq0*4+2][row0] = bReg[0].z; Bs[ns][kq0*4+3][row0] = bReg[0].w;
            As[ns][kq1*4+0][row1] = aReg[1].x; As[ns][kq1*4+1][row1] = aReg[1].y;
            As[ns][kq1*4+2][row1] = aReg[1].z; As[ns][kq1*4+3][row1] = aReg[1].w;
            Bs[ns][kq1*4+0][row1] = bReg[1].x; Bs[ns][kq1*4+1][row1] = bReg[1].y;
            Bs[ns][kq1*4+2][row1] = bReg[1].z; Bs[ns][kq1*4+3][row1] = bReg[1].w;
            __syncthreads();
            s = ns;
        }
    }

    // Epilogue: thresholded gaussian + column sums.
    // cos <= COS_THRESH -> exp underflows to 0 in fp32 (matches reference).
    #pragma unroll
    for (int jp = 0; jp < 4; jp++) {
        float cs0 = 0.0f, cs1 = 0.0f;
        #pragma unroll
        for (int i = 0; i < 8; i++) {
            float c0, c1;
            asm("mov.b64 {%0, %1}, %2;" : "=f"(c0), "=f"(c1) : "l"(acc2[i][jp]));
            if (c0 > COS_THRESH) {
                float dd = c0 - 1.0f;
                cs0 += expf(LOG_NORM - HALF_INV_SIG2 * dd * dd);
            }
            if (c1 > COS_THRESH) {
                float dd = c1 - 1.0f;
                cs1 += expf(LOG_NORM - HALF_INV_SIG2 * dd * dd);
            }
        }
        if (cs0 != 0.0f) atomicAdd(&colAcc[tx * 8 + 2*jp],     cs0);
        if (cs1 != 0.0f) atomicAdd(&colAcc[tx * 8 + 2*jp + 1], cs1);
    }
    __syncthreads();

    if (t < 128) {
        float v = colAcc[t];
        if (v != 0.0f) atomicAdd(&out[mBase + t], v);
    }
}

// ---------------------------------------------------------------------------
extern "C" void kernel_launch(void* const* d_in, const int* in_sizes, int n_in,
                              void* d_out, int out_size)
{
    const float* Ex = (const float*)d_in[0];
    const float* Ey = (const float*)d_in[1];
    float* out = (float*)d_out;

    int N = in_sizes[0] / D;   // 8192
    int M = in_sizes[1] / D;   // 8192

    cudaMemsetAsync(out, 0, (size_t)out_size * sizeof(float));

    int normBlocks = (N + M + 7) / 8;
    normalize_kernel<<<normBlocks, 256>>>(Ex, Ey, N, M);

    dim3 grid(M / 128, N / 128);
    cosexp_gemm<<<grid, 256>>>(N, M, out);
}

// round 4
// speedup vs baseline: 4.6614x; 4.4727x over previous
#include <cuda_runtime.h>
#include <cuda_bf16.h>
#include <cstdint>
#include <math.h>

// ---------------------------------------------------------------------------
// Problem constants
// ---------------------------------------------------------------------------
#define D        256
#define NROWS    8192
#define LOG_NORM 2.0767937f     // -0.5*ln(2*pi) - ln(0.05)
#define HALF_INV_SIG2 200.0f
#define SCREEN_THRESH 0.26f     // fp32 expf()==0 below cos~0.274; bf16 err << margin

#define TILE_N   128            // Ex rows per CTA (MMA M dim)
#define TILE_M   256            // Ey rows per CTA (MMA N dim)
#define BK       64             // bf16 k per chunk = 128 bytes/row
#define NCHUNK   (D / BK)       // 4
#define NT       256            // 8 warps

#define CAP      (1 << 20)

// Scratch (device globals per harness rules)
__device__ float         g_xn[(size_t)NROWS * D];    // normalized fp32
__device__ float         g_yn[(size_t)NROWS * D];
__device__ __nv_bfloat16 g_xb[(size_t)NROWS * D];    // normalized bf16
__device__ __nv_bfloat16 g_yb[(size_t)NROWS * D];
__device__ int           g_cnt;
__device__ int2          g_pairs[CAP];

// ---------------------------------------------------------------------------
// Helpers
// ---------------------------------------------------------------------------
__device__ __forceinline__ uint32_t smem_u32(const void* p) {
    uint32_t a;
    asm("{ .reg .u64 t; cvta.to.shared.u64 t, %1; cvt.u32.u64 %0, t; }" : "=r"(a) : "l"(p));
    return a;
}
#define SWZ(x) ((x) ^ (((x) >> 3) & 0x70))

__device__ __forceinline__ void cp16(uint32_t s, const void* g) {
    uint64_t ga;
    asm("cvta.to.global.u64 %0, %1;" : "=l"(ga) : "l"(g));
    asm volatile("cp.async.cg.shared.global [%0], [%1], 16;" :: "r"(s), "l"(ga) : "memory");
}
#define CP_COMMIT() asm volatile("cp.async.commit_group;" ::: "memory")
#define CP_WAIT(n)  asm volatile("cp.async.wait_group %0;" :: "n"(n) : "memory")

#define LDSM4(r, addr) \
    asm volatile("ldmatrix.sync.aligned.m8n8.x4.shared.b16 {%0,%1,%2,%3}, [%4];" \
        : "=r"((r)[0]), "=r"((r)[1]), "=r"((r)[2]), "=r"((r)[3]) : "r"(addr))

#define MMA16816(ac, a, b0, b1) \
    asm volatile("mma.sync.aligned.m16n8k16.row.col.f32.bf16.bf16.f32 " \
        "{%0,%1,%2,%3},{%4,%5,%6,%7},{%8,%9},{%0,%1,%2,%3};" \
        : "+f"((ac)[0]), "+f"((ac)[1]), "+f"((ac)[2]), "+f"((ac)[3]) \
        : "r"((a)[0]), "r"((a)[1]), "r"((a)[2]), "r"((a)[3]), "r"(b0), "r"(b1))

// SMEM layout: 2 stages, each A[128][128B] + B[256][128B]
#define A_BYTES     (TILE_N * 128)            // 16384
#define B_BYTES     (TILE_M * 128)            // 32768
#define STAGE_BYTES (A_BYTES + B_BYTES)       // 49152
#define SM_A(s)     ((s) * STAGE_BYTES)
#define SM_B(s)     (SM_A(s) + A_BYTES)
#define SMEM_TOTAL  (2 * STAGE_BYTES)         // 98304

// ---------------------------------------------------------------------------
// Normalize rows -> fp32 + bf16 copies. One warp per row. Also resets g_cnt.
// ---------------------------------------------------------------------------
__global__ void __launch_bounds__(256) normsplit_kernel(
    const float* __restrict__ Ex, const float* __restrict__ Ey, int N, int M)
{
    if (blockIdx.x == 0 && threadIdx.x == 0) g_cnt = 0;

    int warp = threadIdx.x >> 5, lane = threadIdx.x & 31;
    int row = blockIdx.x * 8 + warp;
    if (row >= N + M) return;

    const float* src; float* dstf; __nv_bfloat16* dstb; int r;
    if (row < N) { src = Ex; dstf = g_xn; dstb = g_xb; r = row; }
    else         { src = Ey; dstf = g_yn; dstb = g_yb; r = row - N; }

    const float4* s4 = reinterpret_cast<const float4*>(src + (size_t)r * D);
    float4 v0 = s4[lane];
    float4 v1 = s4[lane + 32];

    float ss = v0.x*v0.x + v0.y*v0.y + v0.z*v0.z + v0.w*v0.w
             + v1.x*v1.x + v1.y*v1.y + v1.z*v1.z + v1.w*v1.w;
    #pragma unroll
    for (int off = 16; off > 0; off >>= 1)
        ss += __shfl_xor_sync(0xFFFFFFFFu, ss, off);
    float inv = 1.0f / fmaxf(sqrtf(ss), 1e-8f);

    v0.x *= inv; v0.y *= inv; v0.z *= inv; v0.w *= inv;
    v1.x *= inv; v1.y *= inv; v1.z *= inv; v1.w *= inv;

    float4* d4 = reinterpret_cast<float4*>(dstf + (size_t)r * D);
    d4[lane]      = v0;
    d4[lane + 32] = v1;

    __nv_bfloat16* db = dstb + (size_t)r * D;
    int c0 = lane * 4, c1 = 128 + lane * 4;
    db[c0+0] = __float2bfloat16(v0.x); db[c0+1] = __float2bfloat16(v0.y);
    db[c0+2] = __float2bfloat16(v0.z); db[c0+3] = __float2bfloat16(v0.w);
    db[c1+0] = __float2bfloat16(v1.x); db[c1+1] = __float2bfloat16(v1.y);
    db[c1+2] = __float2bfloat16(v1.z); db[c1+3] = __float2bfloat16(v1.w);
}

// ---------------------------------------------------------------------------
// Screen: bf16 HMMA GEMM (mma.sync), emit candidate pairs with cos > 0.26.
// CTA 128(n) x 256(m); 8 warps, warp tile 64x64; K=256 in 4 chunks of 64.
// ---------------------------------------------------------------------------
__global__ void __launch_bounds__(NT, 1) screen_kernel()
{
    extern __shared__ __align__(1024) char smem[];
    const uint32_t sb = smem_u32(smem);
    const int t = threadIdx.x;
    const int wid = t >> 5, lane = t & 31;
    const int nBase = blockIdx.y * TILE_N;
    const int mBase = blockIdx.x * TILE_M;
    const int nOff = (wid >> 2) * 64;     // warp n offset in tile
    const int mOff = (wid & 3) * 64;      // warp m offset in tile

    const __nv_bfloat16* Xp = g_xb + (size_t)nBase * D;
    const __nv_bfloat16* Yp = g_yb + (size_t)mBase * D;

    float acc[4][8][4];
    #pragma unroll
    for (int mi = 0; mi < 4; mi++)
        #pragma unroll
        for (int j = 0; j < 8; j++)
            #pragma unroll
            for (int r = 0; r < 4; r++) acc[mi][j][r] = 0.0f;

    // cp.async loader for chunk c into stage s. Rows are 128B (64 bf16).
    #define LOAD_CHUNK(c, s) do {                                              \
        int bkb = (c) * 128;                                                   \
        _Pragma("unroll")                                                      \
        for (int i = 0; i < 4; i++) {                                          \
            int idx = t + 256 * i; int r = idx >> 3; int kb = (idx & 7) * 16;  \
            cp16(sb + SM_A(s) + SWZ(r * 128 + kb),                             \
                 (const char*)Xp + (size_t)r * 512 + bkb + kb);                \
        }                                                                      \
        _Pragma("unroll")                                                      \
        for (int i = 0; i < 8; i++) {                                          \
            int idx = t + 256 * i; int r = idx >> 3; int kb = (idx & 7) * 16;  \
            cp16(sb + SM_B(s) + SWZ(r * 128 + kb),                             \
                 (const char*)Yp + (size_t)r * 512 + bkb + kb);                \
        }                                                                      \
        CP_COMMIT();                                                           \
    } while (0)

    LOAD_CHUNK(0, 0);
    LOAD_CHUNK(1, 1);

    // ldmatrix lane addressing (same pattern for A and B x4 loads)
    const int lrow = (lane & 7) + ((lane >> 3) & 1) * 8;
    const int lkb  = (lane >> 4) * 16;

    for (int c = 0; c < NCHUNK; c++) {
        if (c < NCHUNK - 1) CP_WAIT(1); else CP_WAIT(0);
        __syncthreads();
        const int s = c & 1;

        #pragma unroll
        for (int kk = 0; kk < 4; kk++) {          // 4 x k16 per chunk
            uint32_t af[4][4], bf[4][4];
            #pragma unroll
            for (int mi = 0; mi < 4; mi++) {
                uint32_t addr = sb + SM_A(s)
                    + SWZ((nOff + mi * 16 + lrow) * 128 + kk * 32 + lkb);
                LDSM4(af[mi], addr);
            }
            #pragma unroll
            for (int nj = 0; nj < 4; nj++) {
                uint32_t addr = sb + SM_B(s)
                    + SWZ((mOff + nj * 16 + lrow) * 128 + kk * 32 + lkb);
                LDSM4(bf[nj], addr);
            }
            #pragma unroll
            for (int mi = 0; mi < 4; mi++)
                #pragma unroll
                for (int nj = 0; nj < 4; nj++) {
                    MMA16816(acc[mi][2*nj],     af[mi], bf[nj][0], bf[nj][2]);
                    MMA16816(acc[mi][2*nj + 1], af[mi], bf[nj][1], bf[nj][3]);
                }
        }
        __syncthreads();
        if (c + 2 < NCHUNK) LOAD_CHUNK(c + 2, s);
    }

    // Emit candidates. c-frag: r0/r1 -> row lane>>2, cols 2(lane&3)+{0,1};
    //                  r2/r3 -> row (lane>>2)+8, same cols.
    const int rBase = nBase + nOff + (lane >> 2);
    const int cBase = mBase + mOff + 2 * (lane & 3);
    #pragma unroll
    for (int mi = 0; mi < 4; mi++)
        #pragma unroll
        for (int j = 0; j < 8; j++)
            #pragma unroll
            for (int r = 0; r < 4; r++) {
                if (acc[mi][j][r] > SCREEN_THRESH) {
                    int n = rBase + mi * 16 + ((r >> 1) ? 8 : 0);
                    int m = cBase + j * 8 + (r & 1);
                    int idx = atomicAdd(&g_cnt, 1);
                    if (idx < CAP) g_pairs[idx] = make_int2(n, m);
                }
            }
    #undef LOAD_CHUNK
}

// ---------------------------------------------------------------------------
// Exact fp32 recompute of candidates: dot + expf + atomicAdd. 1 warp/pair.
// ---------------------------------------------------------------------------
__global__ void __launch_bounds__(256) recompute_kernel(float* __restrict__ out)
{
    int lane = threadIdx.x & 31;
    int w    = (blockIdx.x * blockDim.x + threadIdx.x) >> 5;
    int nw   = (gridDim.x * blockDim.x) >> 5;
    int cnt  = *(volatile int*)&g_cnt;
    if (cnt > CAP) cnt = CAP;

    for (int i = w; i < cnt; i += nw) {
        int2 p = g_pairs[i];
        const float4* x = reinterpret_cast<const float4*>(g_xn + (size_t)p.x * D);
        const float4* y = reinterpret_cast<const float4*>(g_yn + (size_t)p.y * D);
        float4 xa = x[lane], xb = x[lane + 32];
        float4 ya = y[lane], yb = y[lane + 32];
        float s = xa.x*ya.x + xa.y*ya.y + xa.z*ya.z + xa.w*ya.w
                + xb.x*yb.x + xb.y*yb.y + xb.z*yb.z + xb.w*yb.w;
        #pragma unroll
        for (int off = 16; off > 0; off >>= 1)
            s += __shfl_xor_sync(0xFFFFFFFFu, s, off);
        if (lane == 0) {
            float dd = s - 1.0f;
            float e = expf(LOG_NORM - HALF_INV_SIG2 * dd * dd);
            if (e != 0.0f) atomicAdd(&out[p.y], e);
        }
    }
}

// ---------------------------------------------------------------------------
extern "C" void kernel_launch(void* const* d_in, const int* in_sizes, int n_in,
                              void* d_out, int out_size)
{
    const float* Ex = (const float*)d_in[0];
    const float* Ey = (const float*)d_in[1];
    float* out = (float*)d_out;

    int N = in_sizes[0] / D;   // 8192
    int M = in_sizes[1] / D;   // 8192

    cudaFuncSetAttribute(screen_kernel,
                         cudaFuncAttributeMaxDynamicSharedMemorySize, SMEM_TOTAL);

    cudaMemsetAsync(out, 0, (size_t)out_size * sizeof(float));

    normsplit_kernel<<<(N + M + 7) / 8, 256>>>(Ex, Ey, N, M);

    dim3 grid(M / TILE_M, N / TILE_N);
    screen_kernel<<<grid, NT, SMEM_TOTAL>>>();

    recompute_kernel<<<64, 256>>>(out);
}